// round 1
// baseline (speedup 1.0000x reference)
#include <cuda_runtime.h>
#include <math.h>

// ---------------------------------------------------------------------------
// Decoder step: attention (additive) + 2-layer LSTM + vocab projection
// Shapes: V=32000, E=512, H=1024, A=512, L=2, B=64, S=128
// Output layout (flat f32): logits(64*32000) | new_hidden(2*64*1024) |
//                           new_cell(2*64*1024) | alpha(64*128)
// ---------------------------------------------------------------------------

#define BM 64
#define BN 64
#define BK 16

// Scratch (allocation-free rule: __device__ globals)
__device__ __align__(16) float g_D[64 * 512];      // W_dec proj of top hidden
__device__ __align__(16) float g_score[64 * 128];  // attention scores (b, s)
__device__ __align__(16) float g_x0[64 * 2560];    // [embedded | context]
__device__ __align__(16) float g_xcat[64 * 3072];  // [h1 | context]
__device__ __align__(16) float g_gates[64 * 4096]; // LSTM gate pre-activations

// ---------------------------------------------------------------------------
// Generic tiled GEMM: C[M,N] = A1[M,K1] @ B1[N,K1]^T (+ A2[M,K2] @ B2[N,K2]^T)
//                              (+ bias1[n] + bias2[n])
// Requires: M % 64 == 0 (grid.y = M/64), N % 64 == 0 (grid.x = N/64),
//           K1 % 16 == 0, K2 % 16 == 0. 256 threads, 4x4 microtile.
// ---------------------------------------------------------------------------
__global__ void gemm_dual_kernel(const float* __restrict__ A1, const float* __restrict__ B1, int K1,
                                 const float* __restrict__ A2, const float* __restrict__ B2, int K2,
                                 const float* __restrict__ bias1, const float* __restrict__ bias2,
                                 float* __restrict__ C, int N)
{
    __shared__ float As[BK][BM];
    __shared__ float Bs[BK][BN];
    const int tid = threadIdx.x;
    const int ty = tid >> 4;        // 0..15
    const int tx = tid & 15;        // 0..15
    const int m0 = blockIdx.y * BM;
    const int n0 = blockIdx.x * BN;
    const int lrow = tid >> 2;      // 0..63
    const int lq = (tid & 3) << 2;  // 0,4,8,12

    float acc[4][4];
#pragma unroll
    for (int i = 0; i < 4; i++)
#pragma unroll
        for (int j = 0; j < 4; j++) acc[i][j] = 0.f;

    const int nt1 = K1 / BK;
    const int nt2 = K2 / BK;
    for (int t = 0; t < nt1 + nt2; ++t) {
        const float* A;
        const float* B;
        int K, k0;
        if (t < nt1) { A = A1; B = B1; K = K1; k0 = t * BK; }
        else         { A = A2; B = B2; K = K2; k0 = (t - nt1) * BK; }

        float4 av = *(const float4*)(A + (size_t)(m0 + lrow) * K + k0 + lq);
        float4 bv = *(const float4*)(B + (size_t)(n0 + lrow) * K + k0 + lq);
        As[lq + 0][lrow] = av.x; As[lq + 1][lrow] = av.y;
        As[lq + 2][lrow] = av.z; As[lq + 3][lrow] = av.w;
        Bs[lq + 0][lrow] = bv.x; Bs[lq + 1][lrow] = bv.y;
        Bs[lq + 2][lrow] = bv.z; Bs[lq + 3][lrow] = bv.w;
        __syncthreads();

#pragma unroll
        for (int k = 0; k < BK; k++) {
            float4 a = *(const float4*)(&As[k][ty << 2]);
            float4 b = *(const float4*)(&Bs[k][tx << 2]);
            float ar[4] = {a.x, a.y, a.z, a.w};
            float br[4] = {b.x, b.y, b.z, b.w};
#pragma unroll
            for (int i = 0; i < 4; i++)
#pragma unroll
                for (int j = 0; j < 4; j++)
                    acc[i][j] = fmaf(ar[i], br[j], acc[i][j]);
        }
        __syncthreads();
    }

#pragma unroll
    for (int i = 0; i < 4; i++) {
        int m = m0 + (ty << 2) + i;
        int n = n0 + (tx << 2);
        float4 o;
        o.x = acc[i][0]; o.y = acc[i][1]; o.z = acc[i][2]; o.w = acc[i][3];
        if (bias1) { o.x += bias1[n]; o.y += bias1[n + 1]; o.z += bias1[n + 2]; o.w += bias1[n + 3]; }
        if (bias2) { o.x += bias2[n]; o.y += bias2[n + 1]; o.z += bias2[n + 2]; o.w += bias2[n + 3]; }
        *(float4*)(C + (size_t)m * N + n) = o;
    }
}

// ---------------------------------------------------------------------------
// Energy GEMM with fused attention-score epilogue.
// P[sb, a] = sum_d enc[sb, d] * W_enc[a, d]   (sb = s*64 + b, K = 2048)
// score[b, s] += sum_a tanh(P + D[b, a]) * v[a]
// Grid: (512/64, 8192/64) = (8, 128), 256 threads.
// ---------------------------------------------------------------------------
__global__ void energy_kernel(const float* __restrict__ enc, const float* __restrict__ Wenc,
                              const float* __restrict__ v, float* __restrict__ score)
{
    __shared__ float As[BK][BM];
    __shared__ float Bs[BK][BN];
    const int tid = threadIdx.x;
    const int ty = tid >> 4;
    const int tx = tid & 15;
    const int m0 = blockIdx.y * BM;
    const int n0 = blockIdx.x * BN;
    const int lrow = tid >> 2;
    const int lq = (tid & 3) << 2;
    const int K = 2048;

    float acc[4][4];
#pragma unroll
    for (int i = 0; i < 4; i++)
#pragma unroll
        for (int j = 0; j < 4; j++) acc[i][j] = 0.f;

    for (int t = 0; t < K / BK; ++t) {
        int k0 = t * BK;
        float4 av = *(const float4*)(enc + (size_t)(m0 + lrow) * K + k0 + lq);
        float4 bv = *(const float4*)(Wenc + (size_t)(n0 + lrow) * K + k0 + lq);
        As[lq + 0][lrow] = av.x; As[lq + 1][lrow] = av.y;
        As[lq + 2][lrow] = av.z; As[lq + 3][lrow] = av.w;
        Bs[lq + 0][lrow] = bv.x; Bs[lq + 1][lrow] = bv.y;
        Bs[lq + 2][lrow] = bv.z; Bs[lq + 3][lrow] = bv.w;
        __syncthreads();
#pragma unroll
        for (int k = 0; k < BK; k++) {
            float4 a = *(const float4*)(&As[k][ty << 2]);
            float4 b = *(const float4*)(&Bs[k][tx << 2]);
            float ar[4] = {a.x, a.y, a.z, a.w};
            float br[4] = {b.x, b.y, b.z, b.w};
#pragma unroll
            for (int i = 0; i < 4; i++)
#pragma unroll
                for (int j = 0; j < 4; j++)
                    acc[i][j] = fmaf(ar[i], br[j], acc[i][j]);
        }
        __syncthreads();
    }

    // Fused epilogue: tanh(P + D) . v, reduce over the 64 'a' columns of this
    // tile (4 per thread + 16 tx lanes), atomically accumulate into score.
#pragma unroll
    for (int i = 0; i < 4; i++) {
        int m = m0 + (ty << 2) + i;  // sb
        int b = m & 63;
        int s = m >> 6;
        int n = n0 + (tx << 2);
        float rsum = 0.f;
#pragma unroll
        for (int j = 0; j < 4; j++) {
            int a = n + j;
            rsum += tanhf(acc[i][j] + g_D[b * 512 + a]) * v[a];
        }
        // 16 lanes sharing this row live in one half-warp (lane = (ty&1)*16+tx)
        rsum += __shfl_xor_sync(0xffffffffu, rsum, 8);
        rsum += __shfl_xor_sync(0xffffffffu, rsum, 4);
        rsum += __shfl_xor_sync(0xffffffffu, rsum, 2);
        rsum += __shfl_xor_sync(0xffffffffu, rsum, 1);
        if (tx == 0) atomicAdd(&score[b * 128 + s], rsum);
    }
}

// Softmax over S=128 per batch row; writes alpha straight into d_out.
__global__ void softmax_kernel(const float* __restrict__ score, float* __restrict__ alpha)
{
    __shared__ float sm[128];
    int b = blockIdx.x;
    int t = threadIdx.x;
    float val = score[b * 128 + t];
    sm[t] = val;
    __syncthreads();
    for (int off = 64; off > 0; off >>= 1) {
        if (t < off) sm[t] = fmaxf(sm[t], sm[t + off]);
        __syncthreads();
    }
    float mx = sm[0];
    __syncthreads();
    float e = expf(val - mx);
    sm[t] = e;
    __syncthreads();
    for (int off = 64; off > 0; off >>= 1) {
        if (t < off) sm[t] += sm[t + off];
        __syncthreads();
    }
    alpha[b * 128 + t] = e / sm[0];
}

// context[b, d] = sum_s alpha[b, s] * enc[s, b, d]; writes into x0 and xcat.
__global__ void context_kernel(const float* __restrict__ enc, const float* __restrict__ alpha)
{
    int b = blockIdx.y;
    int d = blockIdx.x * 256 + threadIdx.x;  // 0..2047
    __shared__ float sa[128];
    if (threadIdx.x < 128) sa[threadIdx.x] = alpha[b * 128 + threadIdx.x];
    __syncthreads();
    float sum = 0.f;
#pragma unroll 4
    for (int s = 0; s < 128; s++)
        sum = fmaf(sa[s], enc[((size_t)s * 64 + b) * 2048 + d], sum);
    g_x0[b * 2560 + 512 + d] = sum;
    g_xcat[b * 3072 + 1024 + d] = sum;
}

// Embedding gather into x0[:, 0:512].
__global__ void embed_kernel(const int* __restrict__ token, const float* __restrict__ emb)
{
    int idx = blockIdx.x * 256 + threadIdx.x;  // 64*512
    int b = idx >> 9, e = idx & 511;
    g_x0[b * 2560 + e] = emb[(size_t)token[b] * 512 + e];
}

// LSTM elementwise cell update from g_gates (PyTorch i,f,g,o order).
__global__ void lstm_cell_kernel(const float* __restrict__ c_prev,
                                 float* __restrict__ h_out, float* __restrict__ c_out,
                                 float* __restrict__ h_extra, int extra_stride)
{
    int idx = blockIdx.x * 256 + threadIdx.x;  // 64*1024
    int b = idx >> 10, j = idx & 1023;
    const float* gr = g_gates + b * 4096;
    float ig = gr[j], fg = gr[1024 + j], gg = gr[2048 + j], og = gr[3072 + j];
    float si = 1.f / (1.f + expf(-ig));
    float sf = 1.f / (1.f + expf(-fg));
    float so = 1.f / (1.f + expf(-og));
    float c = sf * c_prev[idx] + si * tanhf(gg);
    float h = so * tanhf(c);
    c_out[idx] = c;
    h_out[idx] = h;
    if (h_extra) h_extra[b * extra_stride + j] = h;
}

extern "C" void kernel_launch(void* const* d_in, const int* in_sizes, int n_in,
                              void* d_out, int out_size)
{
    const int*   token  = (const int*)d_in[0];
    const float* hidden = (const float*)d_in[1];   // (2, 64, 1024)
    const float* cell   = (const float*)d_in[2];   // (2, 64, 1024)
    const float* enc    = (const float*)d_in[3];   // (128, 64, 2048)
    const float* emb    = (const float*)d_in[4];   // (32000, 512)
    const float* W_enc  = (const float*)d_in[5];   // (512, 2048)
    const float* W_dec  = (const float*)d_in[6];   // (512, 1024)
    const float* v_w    = (const float*)d_in[7];   // (512,)
    const float* W_ih0  = (const float*)d_in[8];   // (4096, 2560)
    const float* W_hh0  = (const float*)d_in[9];   // (4096, 1024)
    const float* b_ih0  = (const float*)d_in[10];
    const float* b_hh0  = (const float*)d_in[11];
    const float* W_ih1  = (const float*)d_in[12];  // (4096, 1024)
    const float* W_hh1  = (const float*)d_in[13];  // (4096, 1024)
    const float* b_ih1  = (const float*)d_in[14];
    const float* b_hh1  = (const float*)d_in[15];
    const float* fc_W   = (const float*)d_in[16];  // (32000, 3072)
    const float* fc_b   = (const float*)d_in[17];

    float* out    = (float*)d_out;
    float* logits = out;                       // 64*32000
    float* nh     = out + 2048000;             // 2*64*1024
    float* nc     = out + 2048000 + 131072;    // 2*64*1024
    float* alpha  = out + 2048000 + 262144;    // 64*128

    float *pD, *pScore, *pX0, *pXcat, *pGates;
    cudaGetSymbolAddress((void**)&pD, g_D);
    cudaGetSymbolAddress((void**)&pScore, g_score);
    cudaGetSymbolAddress((void**)&pX0, g_x0);
    cudaGetSymbolAddress((void**)&pXcat, g_xcat);
    cudaGetSymbolAddress((void**)&pGates, g_gates);

    // 1. zero scores (accumulated via atomics in energy epilogue)
    cudaMemsetAsync(pScore, 0, 64 * 128 * sizeof(float));

    // 2. embedding gather (independent)
    embed_kernel<<<128, 256>>>(token, emb);

    // 3. D = top_hidden @ W_dec^T   (64 x 512, K=1024)
    gemm_dual_kernel<<<dim3(8, 1), 256>>>(hidden + 65536, W_dec, 1024,
                                          nullptr, nullptr, 0,
                                          nullptr, nullptr, pD, 512);

    // 4. energy GEMM + fused score reduction  (8192 x 512, K=2048)
    energy_kernel<<<dim3(8, 128), 256>>>(enc, W_enc, v_w, pScore);

    // 5. softmax -> alpha (written directly to output)
    softmax_kernel<<<64, 128>>>(pScore, alpha);

    // 6. context = alpha-weighted sum of enc rows
    context_kernel<<<dim3(8, 64), 256>>>(enc, alpha);

    // 7. LSTM0 gates = x0 @ W_ih0^T + h_prev0 @ W_hh0^T + biases
    gemm_dual_kernel<<<dim3(64, 1), 256>>>(pX0, W_ih0, 2560,
                                           hidden, W_hh0, 1024,
                                           b_ih0, b_hh0, pGates, 4096);
    // 8. LSTM0 cell update -> new_hidden[0], new_cell[0]
    lstm_cell_kernel<<<256, 256>>>(cell, nh, nc, nullptr, 0);

    // 9. LSTM1 gates = h0_new @ W_ih1^T + h_prev1 @ W_hh1^T + biases
    gemm_dual_kernel<<<dim3(64, 1), 256>>>(nh, W_ih1, 1024,
                                           hidden + 65536, W_hh1, 1024,
                                           b_ih1, b_hh1, pGates, 4096);
    // 10. LSTM1 cell update -> new_hidden[1], new_cell[1], h1 into xcat[:, :1024]
    lstm_cell_kernel<<<256, 256>>>(cell + 65536, nh + 65536, nc + 65536, pXcat, 3072);

    // 11. logits = [h1 | context] @ fc_W^T + fc_b   (64 x 32000, K=3072)
    gemm_dual_kernel<<<dim3(500, 1), 256>>>(pXcat, fc_W, 3072,
                                            nullptr, nullptr, 0,
                                            fc_b, nullptr, logits, 32000);
}

// round 2
// speedup vs baseline: 1.4790x; 1.4790x over previous
#include <cuda_runtime.h>
#include <mma.h>
#include <math.h>

using namespace nvcuda;

// ---------------------------------------------------------------------------
// Decoder step: attention (additive) + 2-layer LSTM + vocab projection
// V=32000, E=512, H=1024, A=512, L=2, B=64, S=128
// Output (flat f32): logits(64*32000) | new_hidden(2*64*1024) |
//                    new_cell(2*64*1024) | alpha(64*128)
// ---------------------------------------------------------------------------

// Scratch (allocation-free rule: __device__ globals)
__device__ __align__(16) float g_D[64 * 512];
__device__ __align__(16) float g_score[64 * 128];
__device__ __align__(16) float g_x0[64 * 2560];    // [embedded | context]
__device__ __align__(16) float g_xcat[64 * 3072];  // [h1 | context]
__device__ __align__(16) float g_gates[64 * 4096];

#define LDSM 40   // smem leading dim for 32-wide K staging (+8 pad)
#define LDCS 72   // smem leading dim for 64-wide C tile (+8 pad)

// ---------------------------------------------------------------------------
// tf32 tensor-core GEMM: C[M,N] = A1[M,K1]@B1[N,K1]^T (+A2[M,K2]@B2[N,K2]^T)
//                                 (+bias1[n]+bias2[n])
// grid = (N/64, M/64), 128 threads (4 warps, each warp 32x32 via 2x2 m16n16k8)
// K1, K2 must be multiples of 32.
// ---------------------------------------------------------------------------
__global__ void gemm_tf32_kernel(const float* __restrict__ A1, const float* __restrict__ B1, int K1,
                                 const float* __restrict__ A2, const float* __restrict__ B2, int K2,
                                 const float* __restrict__ bias1, const float* __restrict__ bias2,
                                 float* __restrict__ C, int N)
{
    __shared__ float sbuf[5120];               // 20 KB
    float* As = sbuf;                          // [64][LDSM]
    float* Bs = sbuf + 64 * LDSM;              // [64][LDSM]
    float* Cs = sbuf;                          // [64][LDCS] (reused)

    const int tid = threadIdx.x;
    const int wid = tid >> 5;
    const int wm = (wid >> 1) << 5;            // 0 or 32
    const int wn = (wid & 1) << 5;             // 0 or 32
    const int m0 = blockIdx.y << 6;
    const int n0 = blockIdx.x << 6;

    wmma::fragment<wmma::accumulator, 16, 16, 8, float> acc[2][2];
#pragma unroll
    for (int i = 0; i < 2; i++)
#pragma unroll
        for (int j = 0; j < 2; j++) wmma::fill_fragment(acc[i][j], 0.0f);

    const int nt1 = K1 >> 5;
    const int nt2 = K2 >> 5;
    for (int t = 0; t < nt1 + nt2; ++t) {
        const float* A; const float* B; int K, k0;
        if (t < nt1) { A = A1; B = B1; K = K1; k0 = t << 5; }
        else         { A = A2; B = B2; K = K2; k0 = (t - nt1) << 5; }

#pragma unroll
        for (int r = 0; r < 4; r++) {
            int idx = tid + (r << 7);          // 0..511
            int row = idx >> 3;
            int col = (idx & 7) << 2;
            *(float4*)(As + row * LDSM + col) =
                *(const float4*)(A + (size_t)(m0 + row) * K + k0 + col);
            *(float4*)(Bs + row * LDSM + col) =
                *(const float4*)(B + (size_t)(n0 + row) * K + k0 + col);
        }
        __syncthreads();

#pragma unroll
        for (int kk = 0; kk < 4; kk++) {
            wmma::fragment<wmma::matrix_a, 16, 16, 8, wmma::precision::tf32, wmma::row_major> af[2];
            wmma::fragment<wmma::matrix_b, 16, 16, 8, wmma::precision::tf32, wmma::col_major> bf[2];
#pragma unroll
            for (int i = 0; i < 2; i++) {
                wmma::load_matrix_sync(af[i], As + (wm + (i << 4)) * LDSM + (kk << 3), LDSM);
#pragma unroll
                for (int e = 0; e < af[i].num_elements; e++)
                    af[i].x[e] = wmma::__float_to_tf32(af[i].x[e]);
            }
#pragma unroll
            for (int j = 0; j < 2; j++) {
                wmma::load_matrix_sync(bf[j], Bs + (wn + (j << 4)) * LDSM + (kk << 3), LDSM);
#pragma unroll
                for (int e = 0; e < bf[j].num_elements; e++)
                    bf[j].x[e] = wmma::__float_to_tf32(bf[j].x[e]);
            }
#pragma unroll
            for (int i = 0; i < 2; i++)
#pragma unroll
                for (int j = 0; j < 2; j++)
                    wmma::mma_sync(acc[i][j], af[i], bf[j], acc[i][j]);
        }
        __syncthreads();
    }

#pragma unroll
    for (int i = 0; i < 2; i++)
#pragma unroll
        for (int j = 0; j < 2; j++)
            wmma::store_matrix_sync(Cs + (wm + (i << 4)) * LDCS + wn + (j << 4),
                                    acc[i][j], LDCS, wmma::mem_row_major);
    __syncthreads();

    for (int i = tid; i < 1024; i += 128) {
        int row = i >> 4;
        int c4 = (i & 15) << 2;
        float4 o = *(float4*)(Cs + row * LDCS + c4);
        int n = n0 + c4;
        if (bias1) { o.x += bias1[n]; o.y += bias1[n+1]; o.z += bias1[n+2]; o.w += bias1[n+3]; }
        if (bias2) { o.x += bias2[n]; o.y += bias2[n+1]; o.z += bias2[n+2]; o.w += bias2[n+3]; }
        *(float4*)(C + (size_t)(m0 + row) * N + n) = o;
    }
}

// ---------------------------------------------------------------------------
// Energy GEMM (tf32) with fused attention-score epilogue.
// P[sb,a] = enc[sb,:]@W_enc[a,:]; score[b,s] += sum_a tanh(P+D[b,a])*v[a]
// grid = (512/64, 8192/64), 128 threads.
// ---------------------------------------------------------------------------
__global__ void energy_tf32_kernel(const float* __restrict__ enc, const float* __restrict__ Wenc,
                                   const float* __restrict__ v, float* __restrict__ score)
{
    __shared__ float sbuf[5120];
    float* As = sbuf;
    float* Bs = sbuf + 64 * LDSM;
    float* Cs = sbuf;

    const int tid = threadIdx.x;
    const int wid = tid >> 5;
    const int wm = (wid >> 1) << 5;
    const int wn = (wid & 1) << 5;
    const int m0 = blockIdx.y << 6;
    const int n0 = blockIdx.x << 6;
    const int K = 2048;

    wmma::fragment<wmma::accumulator, 16, 16, 8, float> acc[2][2];
#pragma unroll
    for (int i = 0; i < 2; i++)
#pragma unroll
        for (int j = 0; j < 2; j++) wmma::fill_fragment(acc[i][j], 0.0f);

    for (int t = 0; t < K / 32; ++t) {
        int k0 = t << 5;
#pragma unroll
        for (int r = 0; r < 4; r++) {
            int idx = tid + (r << 7);
            int row = idx >> 3;
            int col = (idx & 7) << 2;
            *(float4*)(As + row * LDSM + col) =
                *(const float4*)(enc + (size_t)(m0 + row) * K + k0 + col);
            *(float4*)(Bs + row * LDSM + col) =
                *(const float4*)(Wenc + (size_t)(n0 + row) * K + k0 + col);
        }
        __syncthreads();

#pragma unroll
        for (int kk = 0; kk < 4; kk++) {
            wmma::fragment<wmma::matrix_a, 16, 16, 8, wmma::precision::tf32, wmma::row_major> af[2];
            wmma::fragment<wmma::matrix_b, 16, 16, 8, wmma::precision::tf32, wmma::col_major> bf[2];
#pragma unroll
            for (int i = 0; i < 2; i++) {
                wmma::load_matrix_sync(af[i], As + (wm + (i << 4)) * LDSM + (kk << 3), LDSM);
#pragma unroll
                for (int e = 0; e < af[i].num_elements; e++)
                    af[i].x[e] = wmma::__float_to_tf32(af[i].x[e]);
            }
#pragma unroll
            for (int j = 0; j < 2; j++) {
                wmma::load_matrix_sync(bf[j], Bs + (wn + (j << 4)) * LDSM + (kk << 3), LDSM);
#pragma unroll
                for (int e = 0; e < bf[j].num_elements; e++)
                    bf[j].x[e] = wmma::__float_to_tf32(bf[j].x[e]);
            }
#pragma unroll
            for (int i = 0; i < 2; i++)
#pragma unroll
                for (int j = 0; j < 2; j++)
                    wmma::mma_sync(acc[i][j], af[i], bf[j], acc[i][j]);
        }
        __syncthreads();
    }

#pragma unroll
    for (int i = 0; i < 2; i++)
#pragma unroll
        for (int j = 0; j < 2; j++)
            wmma::store_matrix_sync(Cs + (wm + (i << 4)) * LDCS + wn + (j << 4),
                                    acc[i][j], LDCS, wmma::mem_row_major);
    __syncthreads();

    // Epilogue: 2 threads per row; each sums tanh(P + D) * v over 32 cols.
    int r = tid >> 1;
    int half = tid & 1;
    int m = m0 + r;
    int b = m & 63;
    int s = m >> 6;
    const float* Crow = Cs + r * LDCS + (half << 5);
    const float* Drow = g_D + b * 512 + n0 + (half << 5);
    const float* vv = v + n0 + (half << 5);
    float sum = 0.f;
#pragma unroll 8
    for (int c = 0; c < 32; c++)
        sum += tanhf(Crow[c] + Drow[c]) * vv[c];
    sum += __shfl_xor_sync(0xffffffffu, sum, 1);
    if (half == 0) atomicAdd(&score[b * 128 + s], sum);
}

// Softmax over S=128 per batch row; writes alpha straight into d_out.
__global__ void softmax_kernel(const float* __restrict__ score, float* __restrict__ alpha)
{
    __shared__ float sm[128];
    int b = blockIdx.x;
    int t = threadIdx.x;
    float val = score[b * 128 + t];
    sm[t] = val;
    __syncthreads();
    for (int off = 64; off > 0; off >>= 1) {
        if (t < off) sm[t] = fmaxf(sm[t], sm[t + off]);
        __syncthreads();
    }
    float mx = sm[0];
    __syncthreads();
    float e = expf(val - mx);
    sm[t] = e;
    __syncthreads();
    for (int off = 64; off > 0; off >>= 1) {
        if (t < off) sm[t] += sm[t + off];
        __syncthreads();
    }
    alpha[b * 128 + t] = e / sm[0];
}

// context[b,d] = sum_s alpha[b,s] * enc[s,b,d]; writes into x0 and xcat.
__global__ void context_kernel(const float* __restrict__ enc, const float* __restrict__ alpha)
{
    int b = blockIdx.y;
    int d = blockIdx.x * 256 + threadIdx.x;  // 0..2047
    __shared__ float sa[128];
    if (threadIdx.x < 128) sa[threadIdx.x] = alpha[b * 128 + threadIdx.x];
    __syncthreads();
    float sum = 0.f;
#pragma unroll 4
    for (int s = 0; s < 128; s++)
        sum = fmaf(sa[s], enc[((size_t)s * 64 + b) * 2048 + d], sum);
    g_x0[b * 2560 + 512 + d] = sum;
    g_xcat[b * 3072 + 1024 + d] = sum;
}

// Embedding gather into x0[:, 0:512].
__global__ void embed_kernel(const int* __restrict__ token, const float* __restrict__ emb)
{
    int idx = blockIdx.x * 256 + threadIdx.x;  // 64*512
    int b = idx >> 9, e = idx & 511;
    g_x0[b * 2560 + e] = emb[(size_t)token[b] * 512 + e];
}

// LSTM elementwise cell update from g_gates (PyTorch i,f,g,o order).
__global__ void lstm_cell_kernel(const float* __restrict__ c_prev,
                                 float* __restrict__ h_out, float* __restrict__ c_out,
                                 float* __restrict__ h_extra, int extra_stride)
{
    int idx = blockIdx.x * 256 + threadIdx.x;  // 64*1024
    int b = idx >> 10, j = idx & 1023;
    const float* gr = g_gates + b * 4096;
    float ig = gr[j], fg = gr[1024 + j], gg = gr[2048 + j], og = gr[3072 + j];
    float si = 1.f / (1.f + expf(-ig));
    float sf = 1.f / (1.f + expf(-fg));
    float so = 1.f / (1.f + expf(-og));
    float c = sf * c_prev[idx] + si * tanhf(gg);
    float h = so * tanhf(c);
    c_out[idx] = c;
    h_out[idx] = h;
    if (h_extra) h_extra[b * extra_stride + j] = h;
}

extern "C" void kernel_launch(void* const* d_in, const int* in_sizes, int n_in,
                              void* d_out, int out_size)
{
    const int*   token  = (const int*)d_in[0];
    const float* hidden = (const float*)d_in[1];   // (2, 64, 1024)
    const float* cell   = (const float*)d_in[2];   // (2, 64, 1024)
    const float* enc    = (const float*)d_in[3];   // (128, 64, 2048)
    const float* emb    = (const float*)d_in[4];   // (32000, 512)
    const float* W_enc  = (const float*)d_in[5];   // (512, 2048)
    const float* W_dec  = (const float*)d_in[6];   // (512, 1024)
    const float* v_w    = (const float*)d_in[7];   // (512,)
    const float* W_ih0  = (const float*)d_in[8];   // (4096, 2560)
    const float* W_hh0  = (const float*)d_in[9];   // (4096, 1024)
    const float* b_ih0  = (const float*)d_in[10];
    const float* b_hh0  = (const float*)d_in[11];
    const float* W_ih1  = (const float*)d_in[12];  // (4096, 1024)
    const float* W_hh1  = (const float*)d_in[13];  // (4096, 1024)
    const float* b_ih1  = (const float*)d_in[14];
    const float* b_hh1  = (const float*)d_in[15];
    const float* fc_W   = (const float*)d_in[16];  // (32000, 3072)
    const float* fc_b   = (const float*)d_in[17];

    float* out    = (float*)d_out;
    float* logits = out;                       // 64*32000
    float* nh     = out + 2048000;             // 2*64*1024
    float* nc     = out + 2048000 + 131072;    // 2*64*1024
    float* alpha  = out + 2048000 + 262144;    // 64*128

    float *pD, *pScore, *pX0, *pXcat, *pGates;
    cudaGetSymbolAddress((void**)&pD, g_D);
    cudaGetSymbolAddress((void**)&pScore, g_score);
    cudaGetSymbolAddress((void**)&pX0, g_x0);
    cudaGetSymbolAddress((void**)&pXcat, g_xcat);
    cudaGetSymbolAddress((void**)&pGates, g_gates);

    // 1. zero scores (accumulated via atomics in energy epilogue)
    cudaMemsetAsync(pScore, 0, 64 * 128 * sizeof(float));

    // 2. embedding gather (independent)
    embed_kernel<<<128, 256>>>(token, emb);

    // 3. D = top_hidden @ W_dec^T   (64 x 512, K=1024)
    gemm_tf32_kernel<<<dim3(8, 1), 128>>>(hidden + 65536, W_dec, 1024,
                                          nullptr, nullptr, 0,
                                          nullptr, nullptr, pD, 512);

    // 4. energy GEMM + fused score reduction  (8192 x 512, K=2048)
    energy_tf32_kernel<<<dim3(8, 128), 128>>>(enc, W_enc, v_w, pScore);

    // 5. softmax -> alpha (written directly to output)
    softmax_kernel<<<64, 128>>>(pScore, alpha);

    // 6. context = alpha-weighted sum of enc rows
    context_kernel<<<dim3(8, 64), 256>>>(enc, alpha);

    // 7. LSTM0 gates = x0 @ W_ih0^T + h_prev0 @ W_hh0^T + biases
    gemm_tf32_kernel<<<dim3(64, 1), 128>>>(pX0, W_ih0, 2560,
                                           hidden, W_hh0, 1024,
                                           b_ih0, b_hh0, pGates, 4096);
    // 8. LSTM0 cell update -> new_hidden[0], new_cell[0]
    lstm_cell_kernel<<<256, 256>>>(cell, nh, nc, nullptr, 0);

    // 9. LSTM1 gates = h0_new @ W_ih1^T + h_prev1 @ W_hh1^T + biases
    gemm_tf32_kernel<<<dim3(64, 1), 128>>>(nh, W_ih1, 1024,
                                           hidden + 65536, W_hh1, 1024,
                                           b_ih1, b_hh1, pGates, 4096);
    // 10. LSTM1 cell update -> new_hidden[1], new_cell[1], h1 into xcat[:, :1024]
    lstm_cell_kernel<<<256, 256>>>(cell + 65536, nh + 65536, nc + 65536, pXcat, 3072);

    // 11. logits = [h1 | context] @ fc_W^T + fc_b   (64 x 32000, K=3072)
    gemm_tf32_kernel<<<dim3(500, 1), 128>>>(pXcat, fc_W, 3072,
                                            nullptr, nullptr, 0,
                                            fc_b, nullptr, logits, 32000);
}

// round 4
// speedup vs baseline: 1.6764x; 1.1335x over previous
#include <cuda_runtime.h>
#include <cstdint>
#include <mma.h>
#include <math.h>

using namespace nvcuda;

// ---------------------------------------------------------------------------
// Decoder step: attention (additive) + 2-layer LSTM + vocab projection
// V=32000, E=512, H=1024, A=512, L=2, B=64, S=128
// Output (flat f32): logits(64*32000) | new_hidden(2*64*1024) |
//                    new_cell(2*64*1024) | alpha(64*128)
// ---------------------------------------------------------------------------

__device__ __align__(16) float g_D[64 * 512];
__device__ __align__(16) float g_score[64 * 128];
__device__ __align__(16) float g_x0[64 * 2560];    // [embedded | context]
__device__ __align__(16) float g_xcat[64 * 3072];  // [h1 | context]
__device__ __align__(16) float g_gates[64 * 4096];

// Tile config: BM=64, BN=128, BK=32, 256 threads (8 warps: 2 m x 4 n, 32x32 each)
#define LDA 40                      // smem row stride for 32-wide tiles (+8 skew)
#define ASZ (64 * LDA)              // 2560 floats
#define BSZ (128 * LDA)             // 5120 floats
#define STG (ASZ + BSZ)             // stage stride: 7680 floats
#define SMEM_BYTES (2 * STG * 4)    // 61440 bytes
#define LDC 136                     // C-tile smem stride

__device__ __forceinline__ void cp_async16(float* smem, const float* gmem) {
    unsigned int s = (unsigned int)__cvta_generic_to_shared(smem);
    asm volatile("cp.async.cg.shared.global [%0], [%1], 16;\n" :: "r"(s), "l"(gmem));
}
__device__ __forceinline__ void cp_commit() { asm volatile("cp.async.commit_group;\n"); }
__device__ __forceinline__ void cp_wait0()  { asm volatile("cp.async.wait_group 0;\n"); }

// Stage one 64x32 A tile + 128x32 B tile into smem via cp.async.
__device__ __forceinline__ void load_tile(float* As, float* Bs,
                                          const float* A, const float* B,
                                          int K, int m0, int n0, int k0, int tid)
{
#pragma unroll
    for (int r = 0; r < 2; r++) {
        int idx = tid + (r << 8);
        int row = idx >> 3, col = (idx & 7) << 2;
        cp_async16(As + row * LDA + col, A + (size_t)(m0 + row) * K + k0 + col);
    }
#pragma unroll
    for (int r = 0; r < 4; r++) {
        int idx = tid + (r << 8);
        int row = idx >> 3, col = (idx & 7) << 2;
        cp_async16(Bs + row * LDA + col, B + (size_t)(n0 + row) * K + k0 + col);
    }
    cp_commit();
}

__device__ __forceinline__ void compute_tile(const float* As, const float* Bs,
    int wm, int wn, wmma::fragment<wmma::accumulator, 16, 16, 8, float> (&acc)[2][2])
{
#pragma unroll
    for (int kk = 0; kk < 4; kk++) {
        wmma::fragment<wmma::matrix_a, 16, 16, 8, wmma::precision::tf32, wmma::row_major> af[2];
        wmma::fragment<wmma::matrix_b, 16, 16, 8, wmma::precision::tf32, wmma::col_major> bf[2];
#pragma unroll
        for (int i = 0; i < 2; i++) {
            wmma::load_matrix_sync(af[i], As + (wm + (i << 4)) * LDA + (kk << 3), LDA);
#pragma unroll
            for (int e = 0; e < af[i].num_elements; e++)
                af[i].x[e] = wmma::__float_to_tf32(af[i].x[e]);
        }
#pragma unroll
        for (int j = 0; j < 2; j++) {
            wmma::load_matrix_sync(bf[j], Bs + (wn + (j << 4)) * LDA + (kk << 3), LDA);
#pragma unroll
            for (int e = 0; e < bf[j].num_elements; e++)
                bf[j].x[e] = wmma::__float_to_tf32(bf[j].x[e]);
        }
#pragma unroll
        for (int i = 0; i < 2; i++)
#pragma unroll
            for (int j = 0; j < 2; j++)
                wmma::mma_sync(acc[i][j], af[i], bf[j], acc[i][j]);
    }
}

// ---------------------------------------------------------------------------
// tf32 GEMM, 2-stage cp.async pipeline.
// C[M,N] = A1[M,K1]@B1^T (+ A2[M,K2]@B2^T) (+ bias1 + bias2)
// ENERGY=true: instead of writing C, fuse score[b,s] += sum_a tanh(C+D)*v[a].
// grid = (N/128, M/64), 256 threads. K1,K2 % 32 == 0.
// ---------------------------------------------------------------------------
template <bool ENERGY>
__global__ void gemm_tc(const float* __restrict__ A1, const float* __restrict__ B1, int K1,
                        const float* __restrict__ A2, const float* __restrict__ B2, int K2,
                        const float* __restrict__ bias1, const float* __restrict__ bias2,
                        float* __restrict__ C, int N,
                        const float* __restrict__ v, float* __restrict__ score)
{
    extern __shared__ float sm[];
    const int tid = threadIdx.x;
    const int wid = tid >> 5;
    const int wm = (wid & 1) << 5;       // 0 or 32
    const int wn = (wid >> 1) << 5;      // 0,32,64,96
    const int m0 = blockIdx.y << 6;
    const int n0 = blockIdx.x << 7;

    wmma::fragment<wmma::accumulator, 16, 16, 8, float> acc[2][2];
#pragma unroll
    for (int i = 0; i < 2; i++)
#pragma unroll
        for (int j = 0; j < 2; j++) wmma::fill_fragment(acc[i][j], 0.0f);

    const int nt1 = K1 >> 5;
    const int nt = nt1 + (K2 >> 5);

    // prologue: stage tile 0
    load_tile(sm, sm + ASZ, A1, B1, K1, m0, n0, 0, tid);

    for (int t = 0; t < nt; ++t) {
        cp_wait0();
        __syncthreads();
        int buf = t & 1;
        if (t + 1 < nt) {
            int u = t + 1;
            const float* A; const float* B; int K, k0;
            if (u < nt1) { A = A1; B = B1; K = K1; k0 = u << 5; }
            else         { A = A2; B = B2; K = K2; k0 = (u - nt1) << 5; }
            float* dst = sm + (u & 1) * STG;
            load_tile(dst, dst + ASZ, A, B, K, m0, n0, k0, tid);
        }
        compute_tile(sm + buf * STG, sm + buf * STG + ASZ, wm, wn, acc);
    }

    __syncthreads();   // all warps done reading stage buffers; reuse smem as C tile
#pragma unroll
    for (int i = 0; i < 2; i++)
#pragma unroll
        for (int j = 0; j < 2; j++)
            wmma::store_matrix_sync(sm + (wm + (i << 4)) * LDC + wn + (j << 4),
                                    acc[i][j], LDC, wmma::mem_row_major);
    __syncthreads();

    if (!ENERGY) {
#pragma unroll
        for (int r = 0; r < 8; r++) {
            int idx = tid + (r << 8);
            int row = idx >> 5;
            int c4 = (idx & 31) << 2;
            float4 o = *(float4*)(sm + row * LDC + c4);
            int n = n0 + c4;
            if (bias1) { o.x += bias1[n]; o.y += bias1[n+1]; o.z += bias1[n+2]; o.w += bias1[n+3]; }
            if (bias2) { o.x += bias2[n]; o.y += bias2[n+1]; o.z += bias2[n+2]; o.w += bias2[n+3]; }
            *(float4*)(C + (size_t)(m0 + row) * N + n) = o;
        }
    } else {
        // score[b,s] += sum over this block's 128 'a' columns of tanh(P+D)*v
        int r = tid >> 2;            // row 0..63
        int q = tid & 3;             // col quarter
        int m = m0 + r;              // sb = s*64 + b
        int b = m & 63;
        int s = m >> 6;
        const float* Crow = sm + r * LDC + (q << 5);
        const float* Drow = g_D + b * 512 + n0 + (q << 5);
        const float* vv = v + n0 + (q << 5);
        float sum = 0.f;
#pragma unroll 8
        for (int c = 0; c < 32; c++)
            sum += tanhf(Crow[c] + Drow[c]) * vv[c];
        sum += __shfl_xor_sync(0xffffffffu, sum, 1);
        sum += __shfl_xor_sync(0xffffffffu, sum, 2);
        if (q == 0) atomicAdd(&score[b * 128 + s], sum);
    }
}

// Softmax over S=128 per batch row; writes alpha straight into d_out.
__global__ void softmax_kernel(const float* __restrict__ score, float* __restrict__ alpha)
{
    __shared__ float sm[128];
    int b = blockIdx.x;
    int t = threadIdx.x;
    float val = score[b * 128 + t];
    sm[t] = val;
    __syncthreads();
    for (int off = 64; off > 0; off >>= 1) {
        if (t < off) sm[t] = fmaxf(sm[t], sm[t + off]);
        __syncthreads();
    }
    float mx = sm[0];
    __syncthreads();
    float e = expf(val - mx);
    sm[t] = e;
    __syncthreads();
    for (int off = 64; off > 0; off >>= 1) {
        if (t < off) sm[t] += sm[t + off];
        __syncthreads();
    }
    alpha[b * 128 + t] = e / sm[0];
}

// context[b,d] = sum_s alpha[b,s] * enc[s,b,d]; writes into x0 and xcat.
__global__ void context_kernel(const float* __restrict__ enc, const float* __restrict__ alpha)
{
    int b = blockIdx.y;
    int d = blockIdx.x * 256 + threadIdx.x;  // 0..2047
    __shared__ float sa[128];
    if (threadIdx.x < 128) sa[threadIdx.x] = alpha[b * 128 + threadIdx.x];
    __syncthreads();
    float sum = 0.f;
#pragma unroll 4
    for (int s = 0; s < 128; s++)
        sum = fmaf(sa[s], enc[((size_t)s * 64 + b) * 2048 + d], sum);
    g_x0[b * 2560 + 512 + d] = sum;
    g_xcat[b * 3072 + 1024 + d] = sum;
}

// Embedding gather into x0[:, 0:512].
__global__ void embed_kernel(const int* __restrict__ token, const float* __restrict__ emb)
{
    int idx = blockIdx.x * 256 + threadIdx.x;  // 64*512
    int b = idx >> 9, e = idx & 511;
    g_x0[b * 2560 + e] = emb[(size_t)token[b] * 512 + e];
}

// LSTM elementwise cell update from g_gates (PyTorch i,f,g,o order).
__global__ void lstm_cell_kernel(const float* __restrict__ c_prev,
                                 float* __restrict__ h_out, float* __restrict__ c_out,
                                 float* __restrict__ h_extra, int extra_stride)
{
    int idx = blockIdx.x * 256 + threadIdx.x;  // 64*1024
    int b = idx >> 10, j = idx & 1023;
    const float* gr = g_gates + b * 4096;
    float ig = gr[j], fg = gr[1024 + j], gg = gr[2048 + j], og = gr[3072 + j];
    float si = 1.f / (1.f + expf(-ig));
    float sf = 1.f / (1.f + expf(-fg));
    float so = 1.f / (1.f + expf(-og));
    float c = sf * c_prev[idx] + si * tanhf(gg);
    float h = so * tanhf(c);
    c_out[idx] = c;
    h_out[idx] = h;
    if (h_extra) h_extra[b * extra_stride + j] = h;
}

extern "C" void kernel_launch(void* const* d_in, const int* in_sizes, int n_in,
                              void* d_out, int out_size)
{
    const int*   token  = (const int*)d_in[0];
    const float* hidden = (const float*)d_in[1];   // (2, 64, 1024)
    const float* cell   = (const float*)d_in[2];   // (2, 64, 1024)
    const float* enc    = (const float*)d_in[3];   // (128, 64, 2048)
    const float* emb    = (const float*)d_in[4];   // (32000, 512)
    const float* W_enc  = (const float*)d_in[5];   // (512, 2048)
    const float* W_dec  = (const float*)d_in[6];   // (512, 1024)
    const float* v_w    = (const float*)d_in[7];   // (512,)
    const float* W_ih0  = (const float*)d_in[8];   // (4096, 2560)
    const float* W_hh0  = (const float*)d_in[9];   // (4096, 1024)
    const float* b_ih0  = (const float*)d_in[10];
    const float* b_hh0  = (const float*)d_in[11];
    const float* W_ih1  = (const float*)d_in[12];  // (4096, 1024)
    const float* W_hh1  = (const float*)d_in[13];  // (4096, 1024)
    const float* b_ih1  = (const float*)d_in[14];
    const float* b_hh1  = (const float*)d_in[15];
    const float* fc_W   = (const float*)d_in[16];  // (32000, 3072)
    const float* fc_b   = (const float*)d_in[17];

    float* out    = (float*)d_out;
    float* logits = out;                       // 64*32000
    float* nh     = out + 2048000;             // 2*64*1024
    float* nc     = out + 2048000 + 131072;    // 2*64*1024
    float* alpha  = out + 2048000 + 262144;    // 64*128

    float *pD, *pScore, *pX0, *pXcat, *pGates;
    cudaGetSymbolAddress((void**)&pD, g_D);
    cudaGetSymbolAddress((void**)&pScore, g_score);
    cudaGetSymbolAddress((void**)&pX0, g_x0);
    cudaGetSymbolAddress((void**)&pXcat, g_xcat);
    cudaGetSymbolAddress((void**)&pGates, g_gates);

    static int smem_set = 0;
    if (!smem_set) {
        cudaFuncSetAttribute(gemm_tc<false>, cudaFuncAttributeMaxDynamicSharedMemorySize, SMEM_BYTES);
        cudaFuncSetAttribute(gemm_tc<true>,  cudaFuncAttributeMaxDynamicSharedMemorySize, SMEM_BYTES);
        smem_set = 1;
    }

    // 1. zero scores (accumulated via atomics in energy epilogue)
    cudaMemsetAsync(pScore, 0, 64 * 128 * sizeof(float));

    // 2. embedding gather (independent)
    embed_kernel<<<128, 256>>>(token, emb);

    // 3. D = top_hidden @ W_dec^T   (64 x 512, K=1024)
    gemm_tc<false><<<dim3(4, 1), 256, SMEM_BYTES>>>(hidden + 65536, W_dec, 1024,
                                                    nullptr, nullptr, 0,
                                                    nullptr, nullptr, pD, 512,
                                                    nullptr, nullptr);

    // 4. energy GEMM + fused score reduction  (8192 x 512, K=2048)
    gemm_tc<true><<<dim3(4, 128), 256, SMEM_BYTES>>>(enc, W_enc, 2048,
                                                     nullptr, nullptr, 0,
                                                     nullptr, nullptr, nullptr, 512,
                                                     v_w, pScore);

    // 5. softmax -> alpha (written directly to output)
    softmax_kernel<<<64, 128>>>(pScore, alpha);

    // 6. context = alpha-weighted sum of enc rows
    context_kernel<<<dim3(8, 64), 256>>>(enc, alpha);

    // 7. LSTM0 gates = x0 @ W_ih0^T + h_prev0 @ W_hh0^T + biases
    gemm_tc<false><<<dim3(32, 1), 256, SMEM_BYTES>>>(pX0, W_ih0, 2560,
                                                     hidden, W_hh0, 1024,
                                                     b_ih0, b_hh0, pGates, 4096,
                                                     nullptr, nullptr);
    // 8. LSTM0 cell update -> new_hidden[0], new_cell[0]
    lstm_cell_kernel<<<256, 256>>>(cell, nh, nc, nullptr, 0);

    // 9. LSTM1 gates = h0_new @ W_ih1^T + h_prev1 @ W_hh1^T + biases
    gemm_tc<false><<<dim3(32, 1), 256, SMEM_BYTES>>>(nh, W_ih1, 1024,
                                                     hidden + 65536, W_hh1, 1024,
                                                     b_ih1, b_hh1, pGates, 4096,
                                                     nullptr, nullptr);
    // 10. LSTM1 cell update -> new_hidden[1], new_cell[1], h1 into xcat
    lstm_cell_kernel<<<256, 256>>>(cell + 65536, nh + 65536, nc + 65536, pXcat, 3072);

    // 11. logits = [h1 | context] @ fc_W^T + fc_b   (64 x 32000, K=3072)
    gemm_tc<false><<<dim3(250, 1), 256, SMEM_BYTES>>>(pXcat, fc_W, 3072,
                                                      nullptr, nullptr, 0,
                                                      fc_b, nullptr, logits, 32000,
                                                      nullptr, nullptr);
}

// round 8
// speedup vs baseline: 3.0890x; 1.8426x over previous
#include <cuda_runtime.h>
#include <cuda_fp16.h>
#include <cstdint>
#include <mma.h>
#include <math.h>

using namespace nvcuda;

// ---------------------------------------------------------------------------
// Decoder step: attention (additive) + 2-layer LSTM + vocab projection
// V=32000, E=512, H=1024, A=512, L=2, B=64, S=128
// Output (flat f32): logits(64*32000) | new_hidden(2*64*1024) |
//                    new_cell(2*64*1024) | alpha(64*128)
// GEMMs: fp16 wmma m16n16k16, f32 accumulate, in-staging f32->f16 convert.
// ---------------------------------------------------------------------------

__device__ __align__(16) float g_D[64 * 512];
__device__ __align__(16) float g_score[64 * 128];
__device__ __align__(16) float g_x0[64 * 2560];    // [embedded | context]
__device__ __align__(16) float g_xcat[64 * 3072];  // [h1 | context]
__device__ __align__(16) float g_gates[64 * 4096];

// Tile: BM=64, BN=256, BK=32. 512 threads = 16 warps (2m x 8n), 32x32/warp.
#define LDH 40                         // smem stride in halfs (+8 skew)
#define ASZH (64 * LDH)                // 2560 halfs
#define BSZH (256 * LDH)               // 10240 halfs
#define STGH (ASZH + BSZH)             // 12800 halfs per stage
#define LDC 264                        // C-tile f32 stride
#define DYN_SMEM 70656                 // max(2*STGH*2, 64*LDC*4) + pad

// ---------------------------------------------------------------------------
// fp16 GEMM: C[M,N] = A1[M,K1]@B1[N,K1]^T (+ A2[M,K2]@B2[N,K2]^T) (+biases)
// EPI=1: energy epilogue -> score[b,s] += sum_a tanh(P + D[b,a]) * v[a]
// grid = (N/256, M/64), 512 threads. K1,K2 % 32 == 0. M_real <= 64.
// ---------------------------------------------------------------------------
template <int EPI>
__global__ void __launch_bounds__(512, 1)
gemm_fp16(const float* __restrict__ A1, const float* __restrict__ B1, int K1,
          const float* __restrict__ A2, const float* __restrict__ B2, int K2,
          const float* __restrict__ bias1, const float* __restrict__ bias2,
          float* __restrict__ C, int N, int M_real,
          const float* __restrict__ v, float* __restrict__ score)
{
    extern __shared__ char smraw[];
    __half* sbuf = (__half*)smraw;
    float* Cs = (float*)smraw;

    const int tid = threadIdx.x;
    const int wid = tid >> 5;
    const int wm = (wid & 1) << 5;        // 0 or 32
    const int wn = (wid >> 1) << 5;       // 0..224
    const int m0 = blockIdx.y << 6;
    const int n0 = blockIdx.x << 8;
    const int arow = tid >> 3;            // 0..63
    const int acol = (tid & 7) << 2;      // 0,4,..,28

    wmma::fragment<wmma::accumulator, 16, 16, 16, float> acc[2][2];
#pragma unroll
    for (int i = 0; i < 2; i++)
#pragma unroll
        for (int j = 0; j < 2; j++) wmma::fill_fragment(acc[i][j], 0.0f);

    const int nt1 = K1 >> 5;
    const int nt = nt1 + (K2 >> 5);

    float4 pa;
    float4 pb[4];

#define LDG_TILE(t_) {                                                        \
        const float* A_; const float* B_; int K_, k0_;                        \
        if ((t_) < nt1) { A_ = A1; B_ = B1; K_ = K1; k0_ = (t_) << 5; }       \
        else            { A_ = A2; B_ = B2; K_ = K2; k0_ = ((t_) - nt1) << 5; } \
        pa = *(const float4*)(A_ + (size_t)(m0 + arow) * K_ + k0_ + acol);    \
        _Pragma("unroll")                                                     \
        for (int i_ = 0; i_ < 4; i_++) {                                      \
            int br_ = (tid + (i_ << 9)) >> 3;                                 \
            pb[i_] = *(const float4*)(B_ + (size_t)(n0 + br_) * K_ + k0_ + acol); \
        } }

#define STS_TILE(b_) {                                                        \
        __half* Ab_ = sbuf + (b_) * STGH;                                     \
        __half* Bb_ = Ab_ + ASZH;                                             \
        __half2* da_ = (__half2*)(Ab_ + arow * LDH + acol);                   \
        da_[0] = __floats2half2_rn(pa.x, pa.y);                               \
        da_[1] = __floats2half2_rn(pa.z, pa.w);                               \
        _Pragma("unroll")                                                     \
        for (int i_ = 0; i_ < 4; i_++) {                                      \
            int br_ = (tid + (i_ << 9)) >> 3;                                 \
            __half2* db_ = (__half2*)(Bb_ + br_ * LDH + acol);                \
            db_[0] = __floats2half2_rn(pb[i_].x, pb[i_].y);                   \
            db_[1] = __floats2half2_rn(pb[i_].z, pb[i_].w);                   \
        } }

    // prologue
    LDG_TILE(0);
    STS_TILE(0);
    __syncthreads();

    for (int t = 0; t < nt; ++t) {
        if (t + 1 < nt) LDG_TILE(t + 1);
        const __half* Ab = sbuf + (t & 1) * STGH;
        const __half* Bb = Ab + ASZH;
#pragma unroll
        for (int kk = 0; kk < 2; kk++) {
            wmma::fragment<wmma::matrix_a, 16, 16, 16, __half, wmma::row_major> af[2];
            wmma::fragment<wmma::matrix_b, 16, 16, 16, __half, wmma::col_major> bf[2];
#pragma unroll
            for (int i = 0; i < 2; i++)
                wmma::load_matrix_sync(af[i], Ab + (wm + (i << 4)) * LDH + (kk << 4), LDH);
#pragma unroll
            for (int j = 0; j < 2; j++)
                wmma::load_matrix_sync(bf[j], Bb + (wn + (j << 4)) * LDH + (kk << 4), LDH);
#pragma unroll
            for (int i = 0; i < 2; i++)
#pragma unroll
                for (int j = 0; j < 2; j++)
                    wmma::mma_sync(acc[i][j], af[i], bf[j], acc[i][j]);
        }
        if (t + 1 < nt) STS_TILE((t + 1) & 1);
        __syncthreads();
    }

#undef LDG_TILE
#undef STS_TILE

    // stash C tile in smem (stage buffers no longer needed)
#pragma unroll
    for (int i = 0; i < 2; i++)
#pragma unroll
        for (int j = 0; j < 2; j++)
            wmma::store_matrix_sync(Cs + (wm + (i << 4)) * LDC + wn + (j << 4),
                                    acc[i][j], LDC, wmma::mem_row_major);
    __syncthreads();

    if (EPI == 0) {
        for (int idx = tid; idx < M_real * 64; idx += 512) {
            int rw = idx >> 6;
            int q = (idx & 63) << 2;
            float4 o = *(float4*)(Cs + rw * LDC + q);
            int n = n0 + q;
            if (bias1) { o.x += bias1[n]; o.y += bias1[n+1]; o.z += bias1[n+2]; o.w += bias1[n+3]; }
            if (bias2) { o.x += bias2[n]; o.y += bias2[n+1]; o.z += bias2[n+2]; o.w += bias2[n+3]; }
            *(float4*)(C + (size_t)(m0 + rw) * N + n) = o;
        }
    } else {
        // energy: this block covers one s (rows = b 0..63), cols n0..n0+255 of A=512.
        // score[b,s] += sum_a tanh(P + D[b,a]) * v[a]
        int rw = tid >> 3;            // b
        int seg = tid & 7;            // 32-col segment
        int s = m0 >> 6;
        const float* Crow = Cs + rw * LDC + (seg << 5);
        const float* Drow = g_D + rw * 512 + n0 + (seg << 5);
        const float* vv = v + n0 + (seg << 5);
        float sum = 0.f;
#pragma unroll 8
        for (int c = 0; c < 32; c++) {
            float t;
            asm("tanh.approx.f32 %0, %1;" : "=f"(t) : "f"(Crow[c] + Drow[c]));
            sum += t * vv[c];
        }
        sum += __shfl_xor_sync(0xffffffffu, sum, 1);
        sum += __shfl_xor_sync(0xffffffffu, sum, 2);
        sum += __shfl_xor_sync(0xffffffffu, sum, 4);
        if (seg == 0) atomicAdd(&score[rw * 128 + s], sum);
    }
}

// ---- small kernels --------------------------------------------------------

// Embedding gather into x0[:, 0:512]; also zeroes the score accumulator.
__global__ void embed_kernel(const int* __restrict__ token, const float* __restrict__ emb)
{
    int idx = blockIdx.x * 256 + threadIdx.x;  // 64*512
    int b = idx >> 9, e = idx & 511;
    g_x0[b * 2560 + e] = emb[(size_t)token[b] * 512 + e];
    if (idx < 64 * 128) g_score[idx] = 0.f;
}

__global__ void softmax_kernel(const float* __restrict__ score, float* __restrict__ alpha)
{
    __shared__ float sm[128];
    int b = blockIdx.x, t = threadIdx.x;
    float val = score[b * 128 + t];
    sm[t] = val;
    __syncthreads();
    for (int off = 64; off > 0; off >>= 1) {
        if (t < off) sm[t] = fmaxf(sm[t], sm[t + off]);
        __syncthreads();
    }
    float mx = sm[0];
    __syncthreads();
    float e = expf(val - mx);
    sm[t] = e;
    __syncthreads();
    for (int off = 64; off > 0; off >>= 1) {
        if (t < off) sm[t] += sm[t + off];
        __syncthreads();
    }
    alpha[b * 128 + t] = e / sm[0];
}

__global__ void context_kernel(const float* __restrict__ enc, const float* __restrict__ alpha)
{
    int b = blockIdx.y;
    int d = blockIdx.x * 256 + threadIdx.x;  // 0..2047
    __shared__ float sa[128];
    if (threadIdx.x < 128) sa[threadIdx.x] = alpha[b * 128 + threadIdx.x];
    __syncthreads();
    float sum = 0.f;
#pragma unroll 4
    for (int s = 0; s < 128; s++)
        sum = fmaf(sa[s], enc[((size_t)s * 64 + b) * 2048 + d], sum);
    g_x0[b * 2560 + 512 + d] = sum;
    g_xcat[b * 3072 + 1024 + d] = sum;
}

__global__ void lstm_cell_kernel(const float* __restrict__ c_prev,
                                 float* __restrict__ h_out, float* __restrict__ c_out,
                                 float* __restrict__ h_extra, int extra_stride)
{
    int idx = blockIdx.x * 256 + threadIdx.x;  // 64*1024
    int b = idx >> 10, j = idx & 1023;
    const float* gr = g_gates + b * 4096;
    float ig = gr[j], fg = gr[1024 + j], gg = gr[2048 + j], og = gr[3072 + j];
    float si = 1.f / (1.f + expf(-ig));
    float sf = 1.f / (1.f + expf(-fg));
    float so = 1.f / (1.f + expf(-og));
    float c = sf * c_prev[idx] + si * tanhf(gg);
    float h = so * tanhf(c);
    c_out[idx] = c;
    h_out[idx] = h;
    if (h_extra) h_extra[b * extra_stride + j] = h;
}

extern "C" void kernel_launch(void* const* d_in, const int* in_sizes, int n_in,
                              void* d_out, int out_size)
{
    const int*   token  = (const int*)d_in[0];
    const float* hidden = (const float*)d_in[1];   // (2, 64, 1024)
    const float* cell   = (const float*)d_in[2];   // (2, 64, 1024)
    const float* enc    = (const float*)d_in[3];   // (128, 64, 2048)
    const float* emb    = (const float*)d_in[4];   // (32000, 512)
    const float* W_enc  = (const float*)d_in[5];   // (512, 2048)
    const float* W_dec  = (const float*)d_in[6];   // (512, 1024)
    const float* v_w    = (const float*)d_in[7];   // (512,)
    const float* W_ih0  = (const float*)d_in[8];   // (4096, 2560)
    const float* W_hh0  = (const float*)d_in[9];   // (4096, 1024)
    const float* b_ih0  = (const float*)d_in[10];
    const float* b_hh0  = (const float*)d_in[11];
    const float* W_ih1  = (const float*)d_in[12];  // (4096, 1024)
    const float* W_hh1  = (const float*)d_in[13];  // (4096, 1024)
    const float* b_ih1  = (const float*)d_in[14];
    const float* b_hh1  = (const float*)d_in[15];
    const float* fc_W   = (const float*)d_in[16];  // (32000, 3072)
    const float* fc_b   = (const float*)d_in[17];

    float* out    = (float*)d_out;
    float* logits = out;                       // 64*32000
    float* nh     = out + 2048000;             // 2*64*1024
    float* nc     = out + 2048000 + 131072;    // 2*64*1024
    float* alpha  = out + 2048000 + 262144;    // 64*128

    float *pD, *pScore, *pX0, *pXcat, *pGates;
    cudaGetSymbolAddress((void**)&pD, g_D);
    cudaGetSymbolAddress((void**)&pScore, g_score);
    cudaGetSymbolAddress((void**)&pX0, g_x0);
    cudaGetSymbolAddress((void**)&pXcat, g_xcat);
    cudaGetSymbolAddress((void**)&pGates, g_gates);

    static int smem_set = 0;
    if (!smem_set) {
        cudaFuncSetAttribute(gemm_fp16<0>, cudaFuncAttributeMaxDynamicSharedMemorySize, DYN_SMEM);
        cudaFuncSetAttribute(gemm_fp16<1>, cudaFuncAttributeMaxDynamicSharedMemorySize, DYN_SMEM);
        smem_set = 1;
    }

    // 1. embedding gather (+score zero)
    embed_kernel<<<128, 256>>>(token, emb);

    // 2. D = top_hidden @ W_dec^T   (64x512, K=1024)
    gemm_fp16<0><<<dim3(2, 1), 512, DYN_SMEM>>>(hidden + 65536, W_dec, 1024,
                                                nullptr, nullptr, 0,
                                                nullptr, nullptr, pD, 512, 64,
                                                nullptr, nullptr);

    // 3. energy GEMM + fused score reduction  (8192x512, K=2048)
    gemm_fp16<1><<<dim3(2, 128), 512, DYN_SMEM>>>(enc, W_enc, 2048,
                                                  nullptr, nullptr, 0,
                                                  nullptr, nullptr, nullptr, 512, 64,
                                                  v_w, pScore);

    // 4. softmax -> alpha
    softmax_kernel<<<64, 128>>>(pScore, alpha);

    // 5. context
    context_kernel<<<dim3(8, 64), 256>>>(enc, alpha);

    // 6. LSTM0 gates = x0@W_ih0^T + h_prev0@W_hh0^T + biases  (64x4096)
    //    (this is the 6th launch -> captured by ncu -s 5 -c 1)
    gemm_fp16<0><<<dim3(16, 1), 512, DYN_SMEM>>>(pX0, W_ih0, 2560,
                                                 hidden, W_hh0, 1024,
                                                 b_ih0, b_hh0, pGates, 4096, 64,
                                                 nullptr, nullptr);

    // 7. LSTM0 cell -> nh[0], nc[0]
    lstm_cell_kernel<<<256, 256>>>(cell, nh, nc, nullptr, 0);

    // 8. LSTM1 gates = h0@W_ih1^T + h_prev1@W_hh1^T + biases
    gemm_fp16<0><<<dim3(16, 1), 512, DYN_SMEM>>>(nh, W_ih1, 1024,
                                                 hidden + 65536, W_hh1, 1024,
                                                 b_ih1, b_hh1, pGates, 4096, 64,
                                                 nullptr, nullptr);

    // 9. LSTM1 cell -> nh[1], nc[1], h1 into xcat[:, :1024]
    lstm_cell_kernel<<<256, 256>>>(cell + 65536, nh + 65536, nc + 65536, pXcat, 3072);

    // 10. logits = [h1 | context] @ fc_W^T + fc_b   (64x32000, K=3072)
    gemm_fp16<0><<<dim3(125, 1), 512, DYN_SMEM>>>(pXcat, fc_W, 3072,
                                                  nullptr, nullptr, 0,
                                                  fc_b, nullptr, logits, 32000, 64,
                                                  nullptr, nullptr);
}